// round 1
// baseline (speedup 1.0000x reference)
#include <cuda_runtime.h>
#include <cstdint>

// Problem dims (fixed by the dataset)
#define BATCH 8
#define CDIM  512
#define NDIM  4096
#define MDIM  1024

// Scratch in __device__ globals (no allocations allowed).
__device__ float g_q[(size_t)BATCH * CDIM * NDIM];   // 64 MB
__device__ float g_k[(size_t)BATCH * CDIM * MDIM];   // 16 MB
__device__ float g_v[(size_t)BATCH * CDIM * MDIM];   // 16 MB
__device__ float g_e[(size_t)BATCH * NDIM * MDIM];   // 128 MB (energy / attention, in-place)

// ---------------------------------------------------------------------------
// Generic batched SGEMM: C[i,j] (+)= alpha * sum_k opA(i,k) * opB(k,j)
//   TA=false: A is [M,K] row-major (A[i*lda+k]);  TA=true: A is [K,M] (A[k*lda+i])
//   TB=false: B is [K,N] row-major (B[k*ldb+j]);  TB=true: B is [N,K] (B[j*ldb+k])
// Tiles: BM=BN=128, BK=16, 256 threads, 8x8 per thread.
// All dims here are multiples of 128/16 so no bounds checks needed.
// ---------------------------------------------------------------------------
template<bool TA, bool TB, bool ACC>
__global__ __launch_bounds__(256, 2)
void gemm128(const float* __restrict__ Ag, const float* __restrict__ Bg,
             float* __restrict__ Cg,
             int Kdim, int lda, int ldb, int ldc,
             size_t sA, size_t sB, size_t sC, float alpha)
{
    constexpr int BM = 128, BN = 128, BK = 16;
    __shared__ float As[BK][BM];
    __shared__ float Bs[BK][BN];

    const float* A = Ag + blockIdx.z * sA;
    const float* B = Bg + blockIdx.z * sB;
    float*       C = Cg + blockIdx.z * sC;

    const int bx = blockIdx.x;   // N tile
    const int by = blockIdx.y;   // M tile
    const int tid = threadIdx.x; // 0..255
    const int tx = tid & 15;     // 0..15 -> 8 cols each
    const int ty = tid >> 4;     // 0..15 -> 8 rows each

    float acc[8][8];
#pragma unroll
    for (int i = 0; i < 8; i++)
#pragma unroll
        for (int j = 0; j < 8; j++) acc[i][j] = 0.f;

    for (int k0 = 0; k0 < Kdim; k0 += BK) {
        // ---- load A tile into As[k][i] ----
        if (!TA) {
            // A[i*lda + k]: read float4 along k, transpose into smem
#pragma unroll
            for (int p = 0; p < 2; p++) {
                int r  = (tid >> 2) + p * 64;     // i in [0,128)
                int cq = (tid & 3) * 4;           // k offset
                float4 v4 = *(const float4*)&A[(size_t)(by * BM + r) * lda + k0 + cq];
                As[cq + 0][r] = v4.x; As[cq + 1][r] = v4.y;
                As[cq + 2][r] = v4.z; As[cq + 3][r] = v4.w;
            }
        } else {
            // A[k*lda + i]: direct coalesced copy
#pragma unroll
            for (int p = 0; p < 2; p++) {
                int r  = (tid >> 5) + p * 8;      // k in [0,16)
                int cq = (tid & 31) * 4;          // i
                *(float4*)&As[r][cq] =
                    *(const float4*)&A[(size_t)(k0 + r) * lda + (size_t)by * BM + cq];
            }
        }
        // ---- load B tile into Bs[k][j] ----
        if (!TB) {
#pragma unroll
            for (int p = 0; p < 2; p++) {
                int r  = (tid >> 5) + p * 8;      // k
                int cq = (tid & 31) * 4;          // j
                *(float4*)&Bs[r][cq] =
                    *(const float4*)&B[(size_t)(k0 + r) * ldb + (size_t)bx * BN + cq];
            }
        } else {
            // B[j*ldb + k]: transpose
#pragma unroll
            for (int p = 0; p < 2; p++) {
                int r  = (tid >> 2) + p * 64;     // j
                int cq = (tid & 3) * 4;           // k
                float4 v4 = *(const float4*)&B[(size_t)(bx * BN + r) * ldb + k0 + cq];
                Bs[cq + 0][r] = v4.x; Bs[cq + 1][r] = v4.y;
                Bs[cq + 2][r] = v4.z; Bs[cq + 3][r] = v4.w;
            }
        }
        __syncthreads();

#pragma unroll
        for (int k = 0; k < BK; k++) {
            float ra[8], rb[8];
            *(float4*)&ra[0] = *(const float4*)&As[k][ty * 8];
            *(float4*)&ra[4] = *(const float4*)&As[k][ty * 8 + 4];
            *(float4*)&rb[0] = *(const float4*)&Bs[k][tx * 8];
            *(float4*)&rb[4] = *(const float4*)&Bs[k][tx * 8 + 4];
#pragma unroll
            for (int i = 0; i < 8; i++)
#pragma unroll
                for (int j = 0; j < 8; j++)
                    acc[i][j] += ra[i] * rb[j];
        }
        __syncthreads();
    }

    // ---- store ----
#pragma unroll
    for (int i = 0; i < 8; i++) {
        size_t row = (size_t)(by * BM + ty * 8 + i);
        float* cp = &C[row * ldc + (size_t)bx * BN + tx * 8];
#pragma unroll
        for (int j = 0; j < 8; j += 4) {
            float4 o;
            o.x = acc[i][j + 0] * alpha;
            o.y = acc[i][j + 1] * alpha;
            o.z = acc[i][j + 2] * alpha;
            o.w = acc[i][j + 3] * alpha;
            if (ACC) {
                float4 prev = *(const float4*)&cp[j];
                o.x += prev.x; o.y += prev.y; o.z += prev.z; o.w += prev.w;
            }
            *(float4*)&cp[j] = o;
        }
    }
}

// ---------------------------------------------------------------------------
// Row softmax over MDIM=1024 columns. One block (256 threads) per row, 4
// elements per thread via float4. In-place.
// ---------------------------------------------------------------------------
__global__ __launch_bounds__(256)
void softmax_rows(float* __restrict__ e)
{
    __shared__ float red[8];
    const size_t row = blockIdx.x;
    float* p = e + row * (size_t)MDIM;
    const int tid = threadIdx.x;

    float4 v4 = ((const float4*)p)[tid];

    // max reduce
    float m = fmaxf(fmaxf(v4.x, v4.y), fmaxf(v4.z, v4.w));
#pragma unroll
    for (int o = 16; o > 0; o >>= 1)
        m = fmaxf(m, __shfl_xor_sync(0xffffffffu, m, o));
    if ((tid & 31) == 0) red[tid >> 5] = m;
    __syncthreads();
    if (tid < 32) {
        float t = (tid < 8) ? red[tid] : -3.4e38f;
#pragma unroll
        for (int o = 4; o > 0; o >>= 1)
            t = fmaxf(t, __shfl_xor_sync(0xffffffffu, t, o));
        if (tid == 0) red[0] = t;
    }
    __syncthreads();
    m = red[0];
    __syncthreads();

    // exp + sum
    v4.x = __expf(v4.x - m);
    v4.y = __expf(v4.y - m);
    v4.z = __expf(v4.z - m);
    v4.w = __expf(v4.w - m);
    float s = v4.x + v4.y + v4.z + v4.w;
#pragma unroll
    for (int o = 16; o > 0; o >>= 1)
        s += __shfl_xor_sync(0xffffffffu, s, o);
    if ((tid & 31) == 0) red[tid >> 5] = s;
    __syncthreads();
    if (tid < 32) {
        float t = (tid < 8) ? red[tid] : 0.f;
#pragma unroll
        for (int o = 4; o > 0; o >>= 1)
            t += __shfl_xor_sync(0xffffffffu, t, o);
        if (tid == 0) red[0] = t;
    }
    __syncthreads();
    float inv = 1.0f / red[0];

    v4.x *= inv; v4.y *= inv; v4.z *= inv; v4.w *= inv;
    ((float4*)p)[tid] = v4;
}

// ---------------------------------------------------------------------------
extern "C" void kernel_launch(void* const* d_in, const int* in_sizes, int n_in,
                              void* d_out, int out_size)
{
    const float* pcd_up   = (const float*)d_in[0]; // [B, C, N]
    const float* pcd_down = (const float*)d_in[1]; // [B, C, M]
    const float* Wq   = (const float*)d_in[2];     // [C, C]
    const float* Wk   = (const float*)d_in[3];
    const float* Wv   = (const float*)d_in[4];
    const float* Wskip= (const float*)d_in[5];
    float* out = (float*)d_out;                    // [B, C, N]

    float* q;  cudaGetSymbolAddress((void**)&q,  g_q);
    float* k;  cudaGetSymbolAddress((void**)&k,  g_k);
    float* v;  cudaGetSymbolAddress((void**)&v,  g_v);
    float* e;  cudaGetSymbolAddress((void**)&e,  g_e);

    const size_t sUp = (size_t)CDIM * NDIM;   // per-batch stride pcd_up / q / out
    const size_t sDn = (size_t)CDIM * MDIM;   // pcd_down / k / v
    const size_t sE  = (size_t)NDIM * MDIM;   // energy

    dim3 thr(256);
    const float invSqrtC = 0.044194173824159216f; // 1/sqrt(512)

    // q = Wq @ pcd_up  (M=C=512, N=NDIM, K=C)
    {
        dim3 grid(NDIM / 128, CDIM / 128, BATCH);
        gemm128<false, false, false><<<grid, thr>>>(Wq, pcd_up, q,
            CDIM, CDIM, NDIM, NDIM, 0, sUp, sUp, 1.0f);
        // skip = Wskip @ pcd_up -> directly into out
        gemm128<false, false, false><<<grid, thr>>>(Wskip, pcd_up, out,
            CDIM, CDIM, NDIM, NDIM, 0, sUp, sUp, 1.0f);
    }
    // k = Wk @ pcd_down ; v = Wv @ pcd_down  (N=MDIM)
    {
        dim3 grid(MDIM / 128, CDIM / 128, BATCH);
        gemm128<false, false, false><<<grid, thr>>>(Wk, pcd_down, k,
            CDIM, CDIM, MDIM, MDIM, 0, sDn, sDn, 1.0f);
        gemm128<false, false, false><<<grid, thr>>>(Wv, pcd_down, v,
            CDIM, CDIM, MDIM, MDIM, 0, sDn, sDn, 1.0f);
    }
    // energy[n,m] = (1/sqrt(C)) * sum_c q[c,n] k[c,m]   (M=NDIM rows, N=MDIM, K=C)
    {
        dim3 grid(MDIM / 128, NDIM / 128, BATCH);
        gemm128<true, false, false><<<grid, thr>>>(q, k, e,
            CDIM, NDIM, MDIM, MDIM, sUp, sDn, sE, invSqrtC);
    }
    // softmax over m, in place
    softmax_rows<<<BATCH * NDIM, 256>>>(e);

    // out[c,n] += sum_m v[c,m] * attn[n,m]   (M=C rows, N=NDIM, K=MDIM)
    {
        dim3 grid(NDIM / 128, CDIM / 128, BATCH);
        gemm128<false, true, true><<<grid, thr>>>(v, e, out,
            MDIM, MDIM, MDIM, NDIM, sDn, sE, sUp, 1.0f);
    }
}